// round 1
// baseline (speedup 1.0000x reference)
#include <cuda_runtime.h>

#define Bsz 256
#define Lsz 500
#define Dsz 3
#define Csz 32
#define Hsz 512
#define Msz 5
#define Isz 35   // D + C
#define Osz 15   // per-mixture out dim * mixtures for mu/sigma
#define OUTsz 35 // 2*O + M

// Scratch (allocation-free rule: __device__ globals). 262 MB each.
__device__ float g_c[Lsz * Bsz * Hsz];
__device__ float g_h[Lsz * Bsz * Hsz];

// ---- packed f32x2 helpers (sm_103a dual-rate fp32 path) ----
__device__ __forceinline__ unsigned long long fma2(unsigned long long a,
                                                   unsigned long long b,
                                                   unsigned long long c) {
    unsigned long long d;
    asm("fma.rn.f32x2 %0, %1, %2, %3;" : "=l"(d) : "l"(a), "l"(b), "l"(c));
    return d;
}
__device__ __forceinline__ unsigned long long pack2(float x, float y) {
    unsigned long long r;
    asm("mov.b64 %0, {%1, %2};" : "=l"(r) : "f"(x), "f"(y));
    return r;
}

// ============================================================
// Kernel A: encoder. c[l,b,h] = sum_i x[l,b,i] * W_enc[l,i,h]
// grid: (B/32, L), block: 256 threads; each thread owns an h-pair,
// holds the 35 W values (as float2) in registers, loops over 32 b.
// ============================================================
__global__ void __launch_bounds__(256) enc_kernel(
    const float* __restrict__ inputs,  // [B, L, D]
    const float* __restrict__ z,       // [B, L, C]
    const float* __restrict__ W)       // [L, I, H]
{
    const int bt = blockIdx.x;   // batch tile (32 rows)
    const int l  = blockIdx.y;
    const int t  = threadIdx.x;

    __shared__ unsigned long long xs2[32 * Isz];  // x duplicated into both lanes

    for (int idx = t; idx < 32 * Isz; idx += 256) {
        int bl = idx / Isz, i = idx % Isz;
        int bg = bt * 32 + bl;
        float v = (i < Dsz) ? inputs[(bg * Lsz + l) * Dsz + i]
                            : z[(bg * Lsz + l) * Csz + (i - Dsz)];
        xs2[idx] = pack2(v, v);
    }
    __syncthreads();

    const int h0 = 2 * t;  // h-pair
    unsigned long long w[Isz];
#pragma unroll
    for (int i = 0; i < Isz; i++) {
        w[i] = *reinterpret_cast<const unsigned long long*>(
            &W[(l * Isz + i) * Hsz + h0]);
    }

    float* cb = &g_c[(l * Bsz + bt * 32) * Hsz + h0];
#pragma unroll 4
    for (int bl = 0; bl < 32; bl++) {
        unsigned long long acc = 0ULL;  // {+0.f, +0.f}
        const unsigned long long* xrow = &xs2[bl * Isz];
#pragma unroll
        for (int i = 0; i < Isz; i++) acc = fma2(xrow[i], w[i], acc);
        *reinterpret_cast<unsigned long long*>(cb + bl * Hsz) = acc;
    }
}

// ============================================================
// Kernel B: exclusive prefix sum over l per (b,h), + b_enc, ReLU.
// h[l] = relu(b_enc + sum_{j<l} c[j]).  131072 threads, 500 iters each.
// ============================================================
__global__ void __launch_bounds__(256) scan_kernel(
    const float* __restrict__ benc)    // [1, H]
{
    const int tid = blockIdx.x * 256 + threadIdx.x;  // 0..131071
    const int b = tid >> 9;     // /512
    const int h = tid & 511;
    const float be = benc[h];
    const int stride = Bsz * Hsz;

    const float* __restrict__ cp = g_c + b * Hsz + h;
    float* __restrict__ hp = g_h + b * Hsz + h;

    float acc = 0.f;
#pragma unroll 4
    for (int l = 0; l < Lsz; l++) {
        float v = cp[l * stride];
        hp[l * stride] = fmaxf(acc + be, 0.f);
        acc += v;
    }
}

// ============================================================
// Kernel C: decoder. out[b,l,o] = sum_h h[l,b,h]*V[l,h,o] + bias
// V = concat(V_mu, V_sigma, V_pi) along o (35 wide).
// grid: (B/32, L), block: 224 = 32 b * 7 o-groups (5 o each).
// K tiled by 128 through shared memory.
// ============================================================
__global__ void __launch_bounds__(224) dec_kernel(
    const float* __restrict__ Vmu,   // [L, H, O]
    const float* __restrict__ bmu,   // [L, 1, O]
    const float* __restrict__ Vsig,  // [L, H, O]
    const float* __restrict__ bsig,  // [L, 1, O]
    const float* __restrict__ Vpi,   // [L, H, M]
    const float* __restrict__ bpi,   // [L, 1, M]
    float* __restrict__ out)         // [B, L, 35]
{
    const int bt = blockIdx.x;
    const int l  = blockIdx.y;
    const int t  = threadIdx.x;

    __shared__ float hs[32][129];   // pad to kill b-stride bank conflicts
    __shared__ float vs[128][36];   // o-combined V tile, padded

    const int b  = t / 7;   // 0..31
    const int og = t % 7;   // 0..6  -> o = og*5 + j

    float acc[5] = {0.f, 0.f, 0.f, 0.f, 0.f};

    for (int k0 = 0; k0 < Hsz; k0 += 128) {
        __syncthreads();
        // stage h tile
        for (int idx = t; idx < 32 * 128; idx += 224) {
            int bl = idx >> 7, kk = idx & 127;
            hs[bl][kk] = g_h[(l * Bsz + bt * 32 + bl) * Hsz + k0 + kk];
        }
        // stage V tile (mu | sigma | pi) -> 35 columns
        for (int idx = t; idx < 128 * 15; idx += 224) {
            int kk = idx / 15, o = idx % 15;
            int g = (l * Hsz + k0 + kk) * Osz + o;
            vs[kk][o]      = Vmu[g];
            vs[kk][15 + o] = Vsig[g];
        }
        for (int idx = t; idx < 128 * 5; idx += 224) {
            int kk = idx / 5, m = idx % 5;
            vs[kk][30 + m] = Vpi[(l * Hsz + k0 + kk) * Msz + m];
        }
        __syncthreads();

#pragma unroll 4
        for (int kk = 0; kk < 128; kk++) {
            float hv = hs[b][kk];
#pragma unroll
            for (int j = 0; j < 5; j++) acc[j] += hv * vs[kk][og * 5 + j];
        }
    }

    const int bg = bt * 32 + b;
    float* op = &out[((size_t)bg * Lsz + l) * OUTsz];
#pragma unroll
    for (int j = 0; j < 5; j++) {
        int o = og * 5 + j;
        float bv = (o < 15) ? bmu[l * Osz + o]
                 : (o < 30) ? bsig[l * Osz + (o - 15)]
                            : bpi[l * Msz + (o - 30)];
        op[o] = acc[j] + bv;
    }
}

extern "C" void kernel_launch(void* const* d_in, const int* in_sizes, int n_in,
                              void* d_out, int out_size) {
    (void)in_sizes; (void)n_in; (void)out_size;
    const float* inputs = (const float*)d_in[0];
    const float* z      = (const float*)d_in[1];
    const float* W_enc  = (const float*)d_in[2];
    const float* b_enc  = (const float*)d_in[3];
    const float* V_mu   = (const float*)d_in[4];
    const float* b_mu   = (const float*)d_in[5];
    const float* V_sig  = (const float*)d_in[6];
    const float* b_sig  = (const float*)d_in[7];
    const float* V_pi   = (const float*)d_in[8];
    const float* b_pi   = (const float*)d_in[9];
    float* out = (float*)d_out;

    enc_kernel<<<dim3(Bsz / 32, Lsz), 256>>>(inputs, z, W_enc);
    scan_kernel<<<(Bsz * Hsz) / 256, 256>>>(b_enc);
    dec_kernel<<<dim3(Bsz / 32, Lsz), 224>>>(V_mu, b_mu, V_sig, b_sig,
                                             V_pi, b_pi, out);
}